// round 4
// baseline (speedup 1.0000x reference)
#include <cuda_runtime.h>
#include <cuda_fp16.h>
#include <cstdint>

#define NB   16
#define CIN  512
#define COUT 512
#define HH   64
#define WWD  64
#define KKC  256   // channel pairs (half2)

// ---------------- device scratch (static, allowed) ----------------
static __device__ float   g_style[NB * CIN];
static __device__ float   g_wsq[COUT * CIN];
static __device__ float   g_demod[NB * COUT];
static __device__ __half2 g_x2[(size_t)NB * KKC * HH * WWD];   // [b][kk][y][x], 67MB
static __device__ __half2 g_wh2[KKC * 9 * COUT];               // [kk][tap][o], 4.7MB

// ---------------- prep kernels ----------------
__global__ void style_kernel(const float* __restrict__ w,
                             const float* __restrict__ mw,
                             const float* __restrict__ mb) {
    __shared__ float sw[512];
    int b = blockIdx.x, c = threadIdx.x;
    sw[c] = w[b * 512 + c];
    __syncthreads();
    float acc = 0.f;
    const float* row = mw + c * 512;
#pragma unroll 8
    for (int d = 0; d < 512; d++) acc += sw[d] * row[d];
    g_style[b * 512 + c] = acc * 0.04419417382415922f + mb[c];
}

__global__ void wsq_kernel(const float* __restrict__ weight) {
    int o = blockIdx.x, c = threadIdx.x;
    const float* p = weight + (o * 512 + c) * 9;
    float s = 0.f;
#pragma unroll
    for (int t = 0; t < 9; t++) { float v = p[t]; s += v * v; }
    g_wsq[o * 512 + c] = s;
}

__global__ void demod_kernel() {
    int gid = blockIdx.x * blockDim.x + threadIdx.x;  // 8192 threads
    int o = gid >> 4, b = gid & 15;
    const float* wq = g_wsq + o * 512;
    const float* st = g_style + b * 512;
    float s = 0.f;
#pragma unroll 8
    for (int c = 0; c < 512; c++) { float t = st[c]; s += wq[c] * t * t; }
    const float WG2 = 1.0f / (512.f * 9.f);
    g_demod[b * 512 + o] = rsqrtf(s * WG2 + 1e-8f);
}

__global__ void xscale_kernel(const float* __restrict__ x) {
    int idx = blockIdx.x * blockDim.x + threadIdx.x;
    int x4 = idx & 15;
    int y  = (idx >> 4) & 63;
    int kk = (idx >> 10) & 255;
    int b  = idx >> 18;
    float se = g_style[b * 512 + 2 * kk];
    float so = g_style[b * 512 + 2 * kk + 1];
    const float4* xp = reinterpret_cast<const float4*>(x);
    float4 xe = xp[(b * 512 + 2 * kk) * 1024 + y * 16 + x4];
    float4 xo = xp[(b * 512 + 2 * kk + 1) * 1024 + y * 16 + x4];
    __half2 h[4];
    h[0] = __floats2half2_rn(xe.x * se, xo.x * so);
    h[1] = __floats2half2_rn(xe.y * se, xo.y * so);
    h[2] = __floats2half2_rn(xe.z * se, xo.z * so);
    h[3] = __floats2half2_rn(xe.w * se, xo.w * so);
    reinterpret_cast<uint4*>(g_x2)[(b * 256 + kk) * 1024 + y * 16 + x4] =
        *reinterpret_cast<uint4*>(h);
}

__global__ void wh2_kernel(const float* __restrict__ weight) {
    int o  = threadIdx.x;
    int kk = blockIdx.x / 9;
    int t  = blockIdx.x % 9;
    const float WG = 0.014731391274719739f;  // 1/sqrt(512*9)
    float we = weight[(o * 512 + 2 * kk) * 9 + t] * WG;
    float wo = weight[(o * 512 + 2 * kk + 1) * 9 + t] * WG;
    g_wh2[(kk * 9 + t) * 512 + o] = __floats2half2_rn(we, wo);
}

// ---------------- conv: implicit GEMM, fp16 mma.sync, fp32 accum ----------------
__device__ __forceinline__ void mma16816(float& c0, float& c1, float& c2, float& c3,
                                         uint32_t a0, uint32_t a1, uint32_t a2, uint32_t a3,
                                         uint32_t b0, uint32_t b1) {
    asm volatile(
        "mma.sync.aligned.m16n8k16.row.col.f32.f16.f16.f32 "
        "{%0,%1,%2,%3}, {%4,%5,%6,%7}, {%8,%9}, {%0,%1,%2,%3};\n"
        : "+f"(c0), "+f"(c1), "+f"(c2), "+f"(c3)
        : "r"(a0), "r"(a1), "r"(a2), "r"(a3), "r"(b0), "r"(b1));
}

__device__ __forceinline__ void cp16(uint32_t dst, const void* src) {
    asm volatile("cp.async.cg.shared.global [%0], [%1], 16;\n" :: "r"(dst), "l"(src));
}
__device__ __forceinline__ void cp_commit() {
    asm volatile("cp.async.commit_group;\n" ::: "memory");
}

#define XS_K 440          // half2 stride per kk slab (6*72 rows + pad), conflict-free
#define XS_R 72           // half2 stride per input row
#define WS_T (16 * 72)    // half2 stride per tap
#define WS_K 72           // half2 stride per kk (64 used; 72 keeps b-loads conflict-free)
#define STAGE (16 * XS_K + 9 * WS_T)   // 17408 half2 = 69632 B per stage

// load one K-chunk (32 input channels) into a stage: X slab + weights, via cp.async
__device__ __forceinline__ void load_chunk(__half2* Xs, __half2* Ws,
                                           int b, int kk0, int y0, int n0, int tid) {
    uint32_t xbase = (uint32_t)__cvta_generic_to_shared(Xs);
    // X: 16 kk x 6 rows x 16 vec16B  (interior cols stored at half2 offset 4..67)
#pragma unroll
    for (int i = 0; i < 6; i++) {
        int idx = tid + i * 256;           // 0..1535
        int v   = idx & 15;
        int t   = idx >> 4;                // 0..95
        int kkL = t / 6;
        int rr  = t - kkL * 6;
        int yy  = y0 - 1 + rr;
        if (yy >= 0 && yy < 64) {
            uint32_t dst = xbase + (uint32_t)(kkL * XS_K + rr * XS_R + 4) * 4u + v * 16u;
            const __half2* src = g_x2 + ((size_t)((b * 256 + kk0 + kkL) * 64 + yy)) * 64 + v * 4;
            cp16(dst, src);
        }
    }
    uint32_t wbase = (uint32_t)__cvta_generic_to_shared(Ws);
    // W: 9 taps x (16 kk x 16 vec16B) ; exactly 256 vecs per tap
#pragma unroll
    for (int tp = 0; tp < 9; tp++) {
        int kkL = tid >> 4;
        int v   = tid & 15;
        uint32_t dst = wbase + (uint32_t)(tp * WS_T + kkL * WS_K) * 4u + v * 16u;
        const __half2* src = g_wh2 + ((size_t)(kk0 + kkL) * 9 + tp) * 512 + n0 + v * 4;
        cp16(dst, src);
    }
}

__global__ void __launch_bounds__(256, 1) conv_kernel(float* __restrict__ out) {
    extern __shared__ __align__(16) __half2 smem[];

    const int n0  = blockIdx.x * 64;
    const int y0  = blockIdx.y * 4;
    const int b   = blockIdx.z;
    const int tid = threadIdx.x;
    const int w = tid >> 5, lane = tid & 31;
    const int g = lane >> 2, t4 = lane & 3;
    const int r = w >> 1, xb = (w & 1) * 32;

    // zero both X slabs once (halo / pad columns stay zero for all chunks)
    {
        uint4 zz = make_uint4(0, 0, 0, 0);
#pragma unroll 1
        for (int st = 0; st < 2; st++) {
            uint4* p = reinterpret_cast<uint4*>(smem + st * STAGE);
            for (int i = tid; i < 16 * XS_K / 4; i += 256) p[i] = zz;
        }
    }
    __syncthreads();

    float acc[64];
#pragma unroll
    for (int i = 0; i < 64; i++) acc[i] = 0.f;

    // prologue: load chunk 0 into stage 0
    load_chunk(smem, smem + 16 * XS_K, b, 0, y0, n0, tid);
    cp_commit();

#pragma unroll 1
    for (int c = 0; c < 16; c++) {
        // issue next chunk's loads into the other stage
        if (c + 1 < 16) {
            __half2* base = smem + ((c + 1) & 1) * STAGE;
            load_chunk(base, base + 16 * XS_K, b, (c + 1) * 16, y0, n0, tid);
            cp_commit();
            asm volatile("cp.async.wait_group 1;\n" ::: "memory");
        } else {
            asm volatile("cp.async.wait_group 0;\n" ::: "memory");
        }
        __syncthreads();

        const __half2* Xs = smem + (c & 1) * STAGE;
        const __half2* Ws = Xs + 16 * XS_K;

#pragma unroll 1
        for (int tap = 0; tap < 9; tap++) {
            const int ky = tap / 3, kx = tap - ky * 3;
#pragma unroll
            for (int ks = 0; ks < 2; ks++) {
                const int kkA = 8 * ks + t4;
                uint32_t a[2][4];
#pragma unroll
                for (int s = 0; s < 2; s++) {
                    int col = 3 + xb + 16 * s + kx + g;   // interior base at half2 col 4, tap kx-1
                    const __half2* base = Xs + kkA * XS_K + (r + ky) * XS_R;
                    a[s][0] = *reinterpret_cast<const uint32_t*>(base + col);
                    a[s][1] = *reinterpret_cast<const uint32_t*>(base + col + 8);
                    a[s][2] = *reinterpret_cast<const uint32_t*>(base + 4 * XS_K + col);
                    a[s][3] = *reinterpret_cast<const uint32_t*>(base + 4 * XS_K + col + 8);
                }
#pragma unroll
                for (int nc = 0; nc < 8; nc++) {
                    const __half2* wb = Ws + tap * WS_T + kkA * WS_K + nc * 8 + g;
                    uint32_t b0 = *reinterpret_cast<const uint32_t*>(wb);
                    uint32_t b1 = *reinterpret_cast<const uint32_t*>(wb + 4 * WS_K);
#pragma unroll
                    for (int s = 0; s < 2; s++) {
                        float* cc = acc + (s * 8 + nc) * 4;
                        mma16816(cc[0], cc[1], cc[2], cc[3],
                                 a[s][0], a[s][1], a[s][2], a[s][3], b0, b1);
                    }
                }
            }
        }
        __syncthreads();   // protect stage (c&1) before it is refilled at iter c+1
    }

    // epilogue: multiply by demod, store fp32
    const int y = y0 + r;
#pragma unroll
    for (int nc = 0; nc < 8; nc++) {
        int o = n0 + nc * 8 + 2 * t4;
        float d0 = g_demod[b * 512 + o];
        float d1 = g_demod[b * 512 + o + 1];
        size_t base0 = (((size_t)b * 512 + o) * 64 + y) * 64;
#pragma unroll
        for (int s = 0; s < 2; s++) {
            int xx = xb + 16 * s + g;
            float* cc = acc + (s * 8 + nc) * 4;
            out[base0 + xx]            = cc[0] * d0;
            out[base0 + 4096 + xx]     = cc[1] * d1;
            out[base0 + xx + 8]        = cc[2] * d0;
            out[base0 + 4096 + xx + 8] = cc[3] * d1;
        }
    }
}

// ---------------- launch ----------------
extern "C" void kernel_launch(void* const* d_in, const int* in_sizes, int n_in,
                              void* d_out, int out_size) {
    const float* x      = (const float*)d_in[0];   // [16,512,64,64]
    const float* w      = (const float*)d_in[1];   // [16,512]
    const float* weight = (const float*)d_in[2];   // [512,512,3,3]
    const float* mw     = (const float*)d_in[3];   // [512,512]
    const float* mb     = (const float*)d_in[4];   // [512]
    float* out = (float*)d_out;

    style_kernel<<<16, 512>>>(w, mw, mb);
    wsq_kernel<<<512, 512>>>(weight);
    demod_kernel<<<32, 256>>>();
    xscale_kernel<<<16384, 256>>>(x);
    wh2_kernel<<<256 * 9, 512>>>(weight);

    size_t shmem = (size_t)(2 * STAGE) * sizeof(__half2);  // 139264 B
    cudaFuncSetAttribute(conv_kernel, cudaFuncAttributeMaxDynamicSharedMemorySize,
                         (int)shmem);
    dim3 grid(8, 16, 16);   // (out-ch/64, H/4, B)
    conv_kernel<<<grid, 256, shmem>>>(out);
}

// round 7
// speedup vs baseline: 1.0210x; 1.0210x over previous
#include <cuda_runtime.h>
#include <cuda_fp16.h>
#include <cstdint>

#define NB   16
#define CIN  512
#define KKC  256   // channel pairs (half2)

static __device__ float   g_style[NB * CIN];
static __device__ float   g_wsq[CIN * CIN];
static __device__ float   g_demod[NB * CIN];
static __device__ __half2 g_x2[(size_t)NB * KKC * 64 * 64];   // [b][kk][y][x]
static __device__ __half2 g_wh2[KKC * 9 * CIN];               // [kk][tap][o]

// ---------------- prep kernels ----------------
__global__ void style_kernel(const float* __restrict__ w,
                             const float* __restrict__ mw,
                             const float* __restrict__ mb) {
    __shared__ float sw[512];
    int b = blockIdx.x, c = threadIdx.x;
    sw[c] = w[b * 512 + c];
    __syncthreads();
    float acc = 0.f;
    const float* row = mw + c * 512;
#pragma unroll 8
    for (int d = 0; d < 512; d++) acc += sw[d] * row[d];
    g_style[b * 512 + c] = acc * 0.04419417382415922f + mb[c];
}
__global__ void wsq_kernel(const float* __restrict__ weight) {
    int o = blockIdx.x, c = threadIdx.x;
    const float* p = weight + (o * 512 + c) * 9;
    float s = 0.f;
#pragma unroll
    for (int t = 0; t < 9; t++) { float v = p[t]; s += v * v; }
    g_wsq[o * 512 + c] = s;
}
__global__ void demod_kernel() {
    int gid = blockIdx.x * blockDim.x + threadIdx.x;
    int o = gid >> 4, b = gid & 15;
    const float* wq = g_wsq + o * 512;
    const float* st = g_style + b * 512;
    float s = 0.f;
#pragma unroll 8
    for (int c = 0; c < 512; c++) { float t = st[c]; s += wq[c] * t * t; }
    g_demod[b * 512 + o] = rsqrtf(s * (1.f / 4608.f) + 1e-8f);
}
__global__ void xscale_kernel(const float* __restrict__ x) {
    int idx = blockIdx.x * blockDim.x + threadIdx.x;
    int x4 = idx & 15;
    int y  = (idx >> 4) & 63;
    int kk = (idx >> 10) & 255;
    int b  = idx >> 18;
    float se = g_style[b * 512 + 2 * kk];
    float so = g_style[b * 512 + 2 * kk + 1];
    const float4* xp = reinterpret_cast<const float4*>(x);
    float4 xe = xp[(b * 512 + 2 * kk) * 1024 + y * 16 + x4];
    float4 xo = xp[(b * 512 + 2 * kk + 1) * 1024 + y * 16 + x4];
    __half2 h[4];
    h[0] = __floats2half2_rn(xe.x * se, xo.x * so);
    h[1] = __floats2half2_rn(xe.y * se, xo.y * so);
    h[2] = __floats2half2_rn(xe.z * se, xo.z * so);
    h[3] = __floats2half2_rn(xe.w * se, xo.w * so);
    reinterpret_cast<uint4*>(g_x2)[(b * 256 + kk) * 1024 + y * 16 + x4] =
        *reinterpret_cast<uint4*>(h);
}
__global__ void wh2_kernel(const float* __restrict__ weight) {
    int o  = threadIdx.x;
    int kk = blockIdx.x / 9;
    int t  = blockIdx.x % 9;
    const float WG = 0.014731391274719739f;  // 1/sqrt(512*9)
    float we = weight[(o * 512 + 2 * kk) * 9 + t] * WG;
    float wo = weight[(o * 512 + 2 * kk + 1) * 9 + t] * WG;
    g_wh2[(kk * 9 + t) * 512 + o] = __floats2half2_rn(we, wo);
}

// ---------------- conv: fp16 mma.sync, occ=2, 3-stage cp.async, 1 sync/chunk ----
__device__ __forceinline__ void mma16816(float& c0, float& c1, float& c2, float& c3,
                                         uint32_t a0, uint32_t a1, uint32_t a2, uint32_t a3,
                                         uint32_t b0, uint32_t b1) {
    asm volatile(
        "mma.sync.aligned.m16n8k16.row.col.f32.f16.f16.f32 "
        "{%0,%1,%2,%3}, {%4,%5,%6,%7}, {%8,%9}, {%0,%1,%2,%3};\n"
        : "+f"(c0), "+f"(c1), "+f"(c2), "+f"(c3)
        : "r"(a0), "r"(a1), "r"(a2), "r"(a3), "r"(b0), "r"(b1));
}
__device__ __forceinline__ void cp16(uint32_t dst, const void* src) {
    asm volatile("cp.async.cg.shared.global [%0], [%1], 16;\n" :: "r"(dst), "l"(src));
}
__device__ __forceinline__ void cp_commit() {
    asm volatile("cp.async.commit_group;\n" ::: "memory");
}

#define XS_K 440            // half2 per kk slab (6*72 + 8 pad)
#define XS_R 72
#define WS_T (8 * 72)       // 576 half2 per tap
#define WS_K 72
#define STAGE (8 * XS_K + 9 * WS_T)   // 8704 half2 = 34816 B

// one K-chunk = 8 kk = 16 input channels
__device__ __forceinline__ void load_chunk8(uint32_t xbase, uint32_t wbase,
                                            int b, int kk0, int y0, int n0, int tid) {
#pragma unroll
    for (int i = 0; i < 3; i++) {               // X: 8 kk x 6 rows x 16 vec = 768
        int idx = tid + i * 256;
        int v = idx & 15, t = idx >> 4;
        int kkL = t / 6, rr = t - kkL * 6;
        int yy = y0 - 1 + rr;
        if (yy >= 0 && yy < 64)
            cp16(xbase + (uint32_t)(kkL * XS_K + rr * XS_R + 4) * 4u + v * 16u,
                 g_x2 + ((size_t)((b * 256 + kk0 + kkL) * 64 + yy)) * 64 + v * 4);
    }
#pragma unroll
    for (int i = 0; i < 5; i++) {               // W: 9 tap x 8 kk x 16 vec = 1152
        int idx = tid + i * 256;
        if (idx < 1152) {
            int v = idx & 15, t = idx >> 4;     // t 0..71
            int tap = t >> 3, kkL = t & 7;
            cp16(wbase + (uint32_t)(tap * WS_T + kkL * WS_K) * 4u + v * 16u,
                 g_wh2 + ((size_t)(kk0 + kkL) * 9 + tap) * 512 + n0 + v * 4);
        }
    }
}

__global__ void __launch_bounds__(256, 2) conv_kernel(float* __restrict__ out) {
    extern __shared__ __align__(16) __half2 smem[];

    const int n0  = blockIdx.x * 64;
    const int y0  = blockIdx.y * 4;
    const int b   = blockIdx.z;
    const int tid = threadIdx.x;
    const int w = tid >> 5, lane = tid & 31;
    const int g = lane >> 2, t4 = lane & 3;
    const int r = w >> 1, xb = (w & 1) * 32;
    const uint32_t sb = (uint32_t)__cvta_generic_to_shared(smem);

    // zero X slabs of all 3 stages once (halo / pad stays zero for all chunks)
    {
        uint4 zz = make_uint4(0, 0, 0, 0);
#pragma unroll 1
        for (int st = 0; st < 3; st++) {
            uint4* p = reinterpret_cast<uint4*>(smem + st * STAGE);
            for (int i = tid; i < 8 * XS_K / 4; i += 256) p[i] = zz;
        }
    }
    __syncthreads();

    float acc[64];
#pragma unroll
    for (int i = 0; i < 64; i++) acc[i] = 0.f;

    // prologue: chunks 0,1 into stages 0,1
#pragma unroll
    for (int p = 0; p < 2; p++) {
        uint32_t xb0 = sb + (uint32_t)(p * STAGE) * 4u;
        load_chunk8(xb0, xb0 + 8 * XS_K * 4u, b, p * 8, y0, n0, tid);
        cp_commit();
    }

#pragma unroll 1
    for (int c = 0; c < 32; c++) {
        if (c < 31) asm volatile("cp.async.wait_group 1;\n" ::: "memory");
        else        asm volatile("cp.async.wait_group 0;\n" ::: "memory");
        __syncthreads();   // compute(c-1) done -> stage (c-1)%3 reusable

        if (c + 2 < 32) {
            uint32_t xb0 = sb + (uint32_t)(((c + 2) % 3) * STAGE) * 4u;
            load_chunk8(xb0, xb0 + 8 * XS_K * 4u, b, (c + 2) * 8, y0, n0, tid);
            cp_commit();
        }

        const __half2* Xs = smem + (c % 3) * STAGE;
        const __half2* Ws = Xs + 8 * XS_K;

#pragma unroll 1
        for (int tap = 0; tap < 9; tap++) {
            const int ky = tap / 3, kx = tap - ky * 3;
            uint32_t a[2][4];
            const __half2* abase = Xs + t4 * XS_K + (r + ky) * XS_R;
#pragma unroll
            for (int s = 0; s < 2; s++) {
                int col = 3 + xb + 16 * s + kx + g;
                a[s][0] = *reinterpret_cast<const uint32_t*>(abase + col);
                a[s][1] = *reinterpret_cast<const uint32_t*>(abase + col + 8);
                a[s][2] = *reinterpret_cast<const uint32_t*>(abase + 4 * XS_K + col);
                a[s][3] = *reinterpret_cast<const uint32_t*>(abase + 4 * XS_K + col + 8);
            }
#pragma unroll
            for (int nc = 0; nc < 8; nc++) {
                const __half2* wb = Ws + tap * WS_T + t4 * WS_K + nc * 8 + g;
                uint32_t b0 = *reinterpret_cast<const uint32_t*>(wb);
                uint32_t b1 = *reinterpret_cast<const uint32_t*>(wb + 4 * WS_K);
#pragma unroll
                for (int s = 0; s < 2; s++) {
                    float* cc = acc + (s * 8 + nc) * 4;
                    mma16816(cc[0], cc[1], cc[2], cc[3],
                             a[s][0], a[s][1], a[s][2], a[s][3], b0, b1);
                }
            }
        }
    }

    // epilogue: demod multiply, fp32 store
    const int y = y0 + r;
#pragma unroll
    for (int nc = 0; nc < 8; nc++) {
        int o = n0 + nc * 8 + 2 * t4;
        float d0 = g_demod[b * 512 + o];
        float d1 = g_demod[b * 512 + o + 1];
        size_t base0 = (((size_t)b * 512 + o) * 64 + y) * 64;
#pragma unroll
        for (int s = 0; s < 2; s++) {
            int xx = xb + 16 * s + g;
            float* cc = acc + (s * 8 + nc) * 4;
            out[base0 + xx]            = cc[0] * d0;
            out[base0 + 4096 + xx]     = cc[1] * d1;
            out[base0 + xx + 8]        = cc[2] * d0;
            out[base0 + 4096 + xx + 8] = cc[3] * d1;
        }
    }
}

// ---------------- launch ----------------
extern "C" void kernel_launch(void* const* d_in, const int* in_sizes, int n_in,
                              void* d_out, int out_size) {
    const float* x      = (const float*)d_in[0];
    const float* w      = (const float*)d_in[1];
    const float* weight = (const float*)d_in[2];
    const float* mw     = (const float*)d_in[3];
    const float* mb     = (const float*)d_in[4];
    float* out = (float*)d_out;

    style_kernel<<<16, 512>>>(w, mw, mb);
    wsq_kernel<<<512, 512>>>(weight);
    demod_kernel<<<32, 256>>>();
    xscale_kernel<<<16384, 256>>>(x);
    wh2_kernel<<<256 * 9, 512>>>(weight);

    int shmem = 3 * STAGE * 4;   // 104448 B -> 2 CTAs/SM
    cudaFuncSetAttribute(conv_kernel, cudaFuncAttributeMaxDynamicSharedMemorySize, shmem);
    dim3 grid(8, 16, 16);
    conv_kernel<<<grid, 256, shmem>>>(out);
}

// round 8
// speedup vs baseline: 1.4541x; 1.4242x over previous
#include <cuda_runtime.h>
#include <cuda_fp16.h>
#include <cstdint>

#define NB 16

static __device__ float   g_style[NB * 512];
static __device__ float   g_wsq[512 * 512];
static __device__ float   g_demod[NB * 512];
static __device__ __half2 g_V[(size_t)16 * 256 * 16384];  // [t][kk][m] 268MB
static __device__ __half2 g_U[(size_t)16 * 256 * 512];    // [t][kk][o]
static __device__ __half2 g_Z[(size_t)16 * 256 * 16384];  // [t][opair][m] 268MB

// ---------------- small prep ----------------
__global__ void style_kernel(const float* __restrict__ w, const float* __restrict__ mw,
                             const float* __restrict__ mb) {
    __shared__ float sw[512];
    int b = blockIdx.x, c = threadIdx.x;
    sw[c] = w[b * 512 + c];
    __syncthreads();
    float acc = 0.f;
    const float* row = mw + c * 512;
#pragma unroll 8
    for (int d = 0; d < 512; d++) acc += sw[d] * row[d];
    g_style[b * 512 + c] = acc * 0.04419417382415922f + mb[c];
}
__global__ void wsq_kernel(const float* __restrict__ weight) {
    int o = blockIdx.x, c = threadIdx.x;
    const float* p = weight + (o * 512 + c) * 9;
    float s = 0.f;
#pragma unroll
    for (int t = 0; t < 9; t++) { float v = p[t]; s += v * v; }
    g_wsq[o * 512 + c] = s;
}
__global__ void demod_kernel() {
    int gid = blockIdx.x * blockDim.x + threadIdx.x;
    int o = gid >> 4, b = gid & 15;
    const float* wq = g_wsq + o * 512;
    const float* st = g_style + b * 512;
    float s = 0.f;
#pragma unroll 8
    for (int c = 0; c < 512; c++) { float t = st[c]; s += wq[c] * t * t; }
    g_demod[b * 512 + o] = rsqrtf(s * (1.f / 4608.f) + 1e-8f);
}

// ---------------- U = G w G^T (weights), fp32 math, fp16 store ----------------
__global__ void ut_kernel(const float* __restrict__ weight) {
    int idx = blockIdx.x * 256 + threadIdx.x;   // 131072
    int o = idx & 511, kk = idx >> 9;
    const float WG = 0.014731391274719739f;     // 1/sqrt(4608)
    float u[2][4][4];
#pragma unroll
    for (int ch = 0; ch < 2; ch++) {
        const float* wp = weight + ((size_t)o * 512 + 2 * kk + ch) * 9;
        float tmp[4][3];
#pragma unroll
        for (int c = 0; c < 3; c++) {
            float w0 = wp[c], w1 = wp[3 + c], w2 = wp[6 + c];
            tmp[0][c] = w0;
            tmp[1][c] = 0.5f * (w0 + w1 + w2);
            tmp[2][c] = 0.5f * (w0 - w1 + w2);
            tmp[3][c] = w2;
        }
#pragma unroll
        for (int i = 0; i < 4; i++) {
            float t0 = tmp[i][0], t1 = tmp[i][1], t2 = tmp[i][2];
            u[ch][i][0] = t0 * WG;
            u[ch][i][1] = 0.5f * (t0 + t1 + t2) * WG;
            u[ch][i][2] = 0.5f * (t0 - t1 + t2) * WG;
            u[ch][i][3] = t2 * WG;
        }
    }
#pragma unroll
    for (int t = 0; t < 16; t++)
        g_U[((size_t)t * 256 + kk) * 512 + o] =
            __floats2half2_rn(u[0][t >> 2][t & 3], u[1][t >> 2][t & 3]);
}

// ---------------- V = B^T (style*x) B, fp32 math, fp16 store ----------------
__device__ __forceinline__ void bt_transform(const float d[4][4], float dt[4][4]) {
    float p[4][4];
#pragma unroll
    for (int j = 0; j < 4; j++) {
        p[0][j] = d[0][j] - d[2][j];
        p[1][j] = d[1][j] + d[2][j];
        p[2][j] = d[2][j] - d[1][j];
        p[3][j] = d[1][j] - d[3][j];
    }
#pragma unroll
    for (int i = 0; i < 4; i++) {
        dt[i][0] = p[i][0] - p[i][2];
        dt[i][1] = p[i][1] + p[i][2];
        dt[i][2] = p[i][2] - p[i][1];
        dt[i][3] = p[i][1] - p[i][3];
    }
}
__global__ void vt_kernel(const float* __restrict__ x) {
    int idx = blockIdx.x * 256 + threadIdx.x;   // 4.19M
    int tile = idx & 1023, kk = (idx >> 10) & 255, b = idx >> 18;
    int ty = tile >> 5, tx = tile & 31;
    int y0 = 2 * ty - 1, x0 = 2 * tx - 1;
    float s0 = g_style[b * 512 + 2 * kk], s1 = g_style[b * 512 + 2 * kk + 1];
    const float* xp0 = x + ((size_t)(b * 512 + 2 * kk)) * 4096;
    const float* xp1 = xp0 + 4096;
    float d0[4][4], d1[4][4];
#pragma unroll
    for (int i = 0; i < 4; i++) {
        int y = y0 + i;
        bool vy = (y >= 0) && (y < 64);
#pragma unroll
        for (int j = 0; j < 4; j++) {
            int xx = x0 + j;
            bool v = vy && (xx >= 0) && (xx < 64);
            d0[i][j] = v ? xp0[y * 64 + xx] * s0 : 0.f;
            d1[i][j] = v ? xp1[y * 64 + xx] * s1 : 0.f;
        }
    }
    float t0[4][4], t1[4][4];
    bt_transform(d0, t0);
    bt_transform(d1, t1);
    size_t m = (size_t)b * 1024 + tile;
#pragma unroll
    for (int t = 0; t < 16; t++)
        g_V[((size_t)t * 256 + kk) * 16384 + m] =
            __floats2half2_rn(t0[t >> 2][t & 3], t1[t >> 2][t & 3]);
}

// ---------------- Winograd-domain GEMM: 16x [16384 x 512 x 512] fp16 mma ----------
__device__ __forceinline__ void mma16816(float& c0, float& c1, float& c2, float& c3,
                                         uint32_t a0, uint32_t a1, uint32_t a2, uint32_t a3,
                                         uint32_t b0, uint32_t b1) {
    asm volatile(
        "mma.sync.aligned.m16n8k16.row.col.f32.f16.f16.f32 "
        "{%0,%1,%2,%3}, {%4,%5,%6,%7}, {%8,%9}, {%0,%1,%2,%3};\n"
        : "+f"(c0), "+f"(c1), "+f"(c2), "+f"(c3)
        : "r"(a0), "r"(a1), "r"(a2), "r"(a3), "r"(b0), "r"(b1));
}
__device__ __forceinline__ void cp16(uint32_t dst, const void* src) {
    asm volatile("cp.async.cg.shared.global [%0], [%1], 16;\n" :: "r"(dst), "l"(src));
}
__device__ __forceinline__ void cp_commit() {
    asm volatile("cp.async.commit_group;\n" ::: "memory");
}

#define AS_K 264                    // half2 stride per kk (256 + 8 pad)
#define BS_K 72                     // half2 stride per kk (64 + 8 pad)
#define STGH (8 * AS_K + 8 * BS_K)  // 2688 half2 = 10752 B per stage

__global__ void __launch_bounds__(256, 2) wg_kernel() {
    extern __shared__ __align__(16) __half2 sm[];
    const int t  = blockIdx.z;
    const int n0 = blockIdx.y * 64;
    const int MB0 = blockIdx.x * 256;
    const int tid = threadIdx.x, w = tid >> 5, lane = tid & 31;
    const int g = lane >> 2, t4 = lane & 3;
    const uint32_t sb = (uint32_t)__cvta_generic_to_shared(sm);

    float acc[64];
#pragma unroll
    for (int i = 0; i < 64; i++) acc[i] = 0.f;

    auto load = [&](int kc, int st) {
        uint32_t base = sb + (uint32_t)(st * STGH) * 4u;
#pragma unroll
        for (int i = 0; i < 2; i++) {                       // A: 512 vec16
            int id2 = tid + i * 256;
            int kkL = id2 >> 6, v = id2 & 63;
            cp16(base + (uint32_t)(kkL * AS_K) * 4u + v * 16u,
                 g_V + ((size_t)(t * 256 + kc * 8 + kkL)) * 16384 + MB0 + v * 4);
        }
        if (tid < 128) {                                    // B: 128 vec16
            int kkL = tid >> 4, v = tid & 15;
            cp16(base + (uint32_t)(8 * AS_K + kkL * BS_K) * 4u + v * 16u,
                 g_U + ((size_t)(t * 256 + kc * 8 + kkL)) * 512 + n0 + v * 4);
        }
    };
    load(0, 0); cp_commit();
    load(1, 1); cp_commit();
    load(2, 2); cp_commit();

#pragma unroll 1
    for (int c = 0; c < 32; c++) {
        if (c <= 29)      asm volatile("cp.async.wait_group 2;\n" ::: "memory");
        else if (c == 30) asm volatile("cp.async.wait_group 1;\n" ::: "memory");
        else              asm volatile("cp.async.wait_group 0;\n" ::: "memory");
        __syncthreads();
        if (c + 3 < 32) { load(c + 3, (c + 3) & 3); cp_commit(); }

        const __half2* As = sm + (c & 3) * STGH;
        const __half2* Bs = As + 8 * AS_K;
        uint32_t a[2][4];
#pragma unroll
        for (int s = 0; s < 2; s++) {
            int mc = w * 32 + s * 16 + g;
            const __half2* ab = As + t4 * AS_K + mc;
            a[s][0] = *reinterpret_cast<const uint32_t*>(ab);
            a[s][1] = *reinterpret_cast<const uint32_t*>(ab + 8);
            a[s][2] = *reinterpret_cast<const uint32_t*>(ab + 4 * AS_K);
            a[s][3] = *reinterpret_cast<const uint32_t*>(ab + 4 * AS_K + 8);
        }
#pragma unroll
        for (int nc = 0; nc < 8; nc++) {
            const __half2* bb = Bs + t4 * BS_K + nc * 8 + g;
            uint32_t b0 = *reinterpret_cast<const uint32_t*>(bb);
            uint32_t b1 = *reinterpret_cast<const uint32_t*>(bb + 4 * BS_K);
#pragma unroll
            for (int s = 0; s < 2; s++) {
                float* cc = acc + (s * 8 + nc) * 4;
                mma16816(cc[0], cc[1], cc[2], cc[3],
                         a[s][0], a[s][1], a[s][2], a[s][3], b0, b1);
            }
        }
    }

    // epilogue: fp16 Z, half2 = (cout even, cout odd)
#pragma unroll
    for (int s = 0; s < 2; s++) {
        int m0 = MB0 + w * 32 + s * 16 + g;
#pragma unroll
        for (int nc = 0; nc < 8; nc++) {
            int opair = (n0 + nc * 8) / 2 + t4;
            float* cc = acc + (s * 8 + nc) * 4;
            size_t zi = ((size_t)(t * 256 + opair)) * 16384;
            g_Z[zi + m0]     = __floats2half2_rn(cc[0], cc[1]);
            g_Z[zi + m0 + 8] = __floats2half2_rn(cc[2], cc[3]);
        }
    }
}

// ---------------- output transform: out = A^T M A * demod ----------------
__global__ void ot_kernel(float* __restrict__ out) {
    int idx = blockIdx.x * 256 + threadIdx.x;   // 4.19M
    int tile = idx & 1023, opair = (idx >> 10) & 255, b = idx >> 18;
    int ty = tile >> 5, tx = tile & 31;
    size_t m = (size_t)b * 1024 + tile;
    float Ml[16], Mh[16];
#pragma unroll
    for (int t = 0; t < 16; t++) {
        __half2 h = g_Z[((size_t)t * 256 + opair) * 16384 + m];
        Ml[t] = __low2float(h);
        Mh[t] = __high2float(h);
    }
    int o = opair * 2;
    float dm0 = g_demod[b * 512 + o], dm1 = g_demod[b * 512 + o + 1];
    float* op = out + (((size_t)b * 512 + o) * 64 + 2 * ty) * 64 + 2 * tx;

#pragma unroll
    for (int ch = 0; ch < 2; ch++) {
        const float* M = ch ? Mh : Ml;
        float dm = ch ? dm1 : dm0;
        float T0[4], T1[4];
#pragma unroll
        for (int j = 0; j < 4; j++) {
            T0[j] = M[j] + M[4 + j] + M[8 + j];
            T1[j] = M[4 + j] - M[8 + j] - M[12 + j];
        }
        float o00 = (T0[0] + T0[1] + T0[2]) * dm;
        float o01 = (T0[1] - T0[2] - T0[3]) * dm;
        float o10 = (T1[0] + T1[1] + T1[2]) * dm;
        float o11 = (T1[1] - T1[2] - T1[3]) * dm;
        float* q = op + (size_t)ch * 4096;
        *reinterpret_cast<float2*>(q)      = make_float2(o00, o01);
        *reinterpret_cast<float2*>(q + 64) = make_float2(o10, o11);
    }
}

// ---------------- launch ----------------
extern "C" void kernel_launch(void* const* d_in, const int* in_sizes, int n_in,
                              void* d_out, int out_size) {
    const float* x      = (const float*)d_in[0];
    const float* w      = (const float*)d_in[1];
    const float* weight = (const float*)d_in[2];
    const float* mw     = (const float*)d_in[3];
    const float* mb     = (const float*)d_in[4];
    float* out = (float*)d_out;

    style_kernel<<<16, 512>>>(w, mw, mb);
    wsq_kernel<<<512, 512>>>(weight);
    demod_kernel<<<32, 256>>>();
    ut_kernel<<<512, 256>>>(weight);
    vt_kernel<<<16384, 256>>>(x);

    dim3 grid(64, 8, 16);   // (M/256, N/64, t)
    wg_kernel<<<grid, 256, 4 * STGH * 4>>>();

    ot_kernel<<<16384, 256>>>(out);
}

// round 9
// speedup vs baseline: 1.4638x; 1.0066x over previous
#include <cuda_runtime.h>
#include <cuda_fp16.h>
#include <cstdint>

#define NB 16

static __device__ float   g_style[NB * 512];
static __device__ float   g_wsq[512 * 512];
static __device__ float   g_demod[NB * 512];
static __device__ __half2 g_V[(size_t)16 * 256 * 16384];  // [t][kk][m]
static __device__ __half2 g_U[(size_t)16 * 256 * 512];    // [t][kk][o]
static __device__ __half2 g_Z[(size_t)16 * 256 * 16384];  // [t][opair][m]

// ---------------- small prep ----------------
__global__ void style_kernel(const float* __restrict__ w, const float* __restrict__ mw,
                             const float* __restrict__ mb) {
    __shared__ float sw[512];
    int b = blockIdx.x, c = threadIdx.x;
    sw[c] = w[b * 512 + c];
    __syncthreads();
    float acc = 0.f;
    const float* row = mw + c * 512;
#pragma unroll 8
    for (int d = 0; d < 512; d++) acc += sw[d] * row[d];
    g_style[b * 512 + c] = acc * 0.04419417382415922f + mb[c];
}
__global__ void wsq_kernel(const float* __restrict__ weight) {
    int o = blockIdx.x, c = threadIdx.x;
    const float* p = weight + (o * 512 + c) * 9;
    float s = 0.f;
#pragma unroll
    for (int t = 0; t < 9; t++) { float v = p[t]; s += v * v; }
    g_wsq[o * 512 + c] = s;
}
__global__ void demod_kernel() {
    int gid = blockIdx.x * blockDim.x + threadIdx.x;
    int o = gid >> 4, b = gid & 15;
    const float* wq = g_wsq + o * 512;
    const float* st = g_style + b * 512;
    float s = 0.f;
#pragma unroll 8
    for (int c = 0; c < 512; c++) { float t = st[c]; s += wq[c] * t * t; }
    g_demod[b * 512 + o] = rsqrtf(s * (1.f / 4608.f) + 1e-8f);
}

// ---------------- U = G w G^T ----------------
__global__ void ut_kernel(const float* __restrict__ weight) {
    int idx = blockIdx.x * 256 + threadIdx.x;
    int o = idx & 511, kk = idx >> 9;
    const float WG = 0.014731391274719739f;
    float u[2][4][4];
#pragma unroll
    for (int ch = 0; ch < 2; ch++) {
        const float* wp = weight + ((size_t)o * 512 + 2 * kk + ch) * 9;
        float tmp[4][3];
#pragma unroll
        for (int c = 0; c < 3; c++) {
            float w0 = wp[c], w1 = wp[3 + c], w2 = wp[6 + c];
            tmp[0][c] = w0;
            tmp[1][c] = 0.5f * (w0 + w1 + w2);
            tmp[2][c] = 0.5f * (w0 - w1 + w2);
            tmp[3][c] = w2;
        }
#pragma unroll
        for (int i = 0; i < 4; i++) {
            float t0 = tmp[i][0], t1 = tmp[i][1], t2 = tmp[i][2];
            u[ch][i][0] = t0 * WG;
            u[ch][i][1] = 0.5f * (t0 + t1 + t2) * WG;
            u[ch][i][2] = 0.5f * (t0 - t1 + t2) * WG;
            u[ch][i][3] = t2 * WG;
        }
    }
#pragma unroll
    for (int t = 0; t < 16; t++)
        g_U[((size_t)t * 256 + kk) * 512 + o] =
            __floats2half2_rn(u[0][t >> 2][t & 3], u[1][t >> 2][t & 3]);
}

// ---------------- V = B^T (style*x) B : 4 tiles/thread, vectorized ----------------
__global__ void __launch_bounds__(256) vt_kernel(const float* __restrict__ x) {
    int idx = blockIdx.x * 256 + threadIdx.x;   // 1,048,576
    int q  = idx & 7;
    int ty = (idx >> 3) & 31;
    int kk = (idx >> 8) & 255;
    int b  = idx >> 16;
    float s[2];
    s[0] = g_style[b * 512 + 2 * kk];
    s[1] = g_style[b * 512 + 2 * kk + 1];

    float f0[16][4];      // ch0 fp32 results [t][tile]
    __half2 hv[16][4];    // packed results

#pragma unroll
    for (int ch = 0; ch < 2; ch++) {
        const float* xp = x + ((size_t)(b * 512 + 2 * kk + ch)) * 4096;
        float d[4][10];
        int y0 = 2 * ty - 1;
        int xl = 8 * q - 1;
#pragma unroll
        for (int r = 0; r < 4; r++) {
            int y = y0 + r;
            bool vy = (y >= 0) && (y < 64);
            const float* row = xp + y * 64;
            float4 A = make_float4(0.f, 0.f, 0.f, 0.f), B = A;
            if (vy) {
                A = *reinterpret_cast<const float4*>(row + 8 * q);
                B = *reinterpret_cast<const float4*>(row + 8 * q + 4);
            }
            float sc = s[ch];
            d[r][0] = (vy && q > 0) ? row[xl] * sc : 0.f;
            d[r][1] = A.x * sc; d[r][2] = A.y * sc; d[r][3] = A.z * sc; d[r][4] = A.w * sc;
            d[r][5] = B.x * sc; d[r][6] = B.y * sc; d[r][7] = B.z * sc; d[r][8] = B.w * sc;
            d[r][9] = (vy && q < 7) ? row[8 * q + 8] * sc : 0.f;
        }
        float p[4][10];
#pragma unroll
        for (int c = 0; c < 10; c++) {
            p[0][c] = d[0][c] - d[2][c];
            p[1][c] = d[1][c] + d[2][c];
            p[2][c] = d[2][c] - d[1][c];
            p[3][c] = d[1][c] - d[3][c];
        }
#pragma unroll
        for (int dt = 0; dt < 4; dt++) {
            int cl = 2 * dt;
#pragma unroll
            for (int i = 0; i < 4; i++) {
                float v0 = p[i][cl]     - p[i][cl + 2];
                float v1 = p[i][cl + 1] + p[i][cl + 2];
                float v2 = p[i][cl + 2] - p[i][cl + 1];
                float v3 = p[i][cl + 1] - p[i][cl + 3];
                if (ch == 0) {
                    f0[4 * i + 0][dt] = v0; f0[4 * i + 1][dt] = v1;
                    f0[4 * i + 2][dt] = v2; f0[4 * i + 3][dt] = v3;
                } else {
                    hv[4 * i + 0][dt] = __floats2half2_rn(f0[4 * i + 0][dt], v0);
                    hv[4 * i + 1][dt] = __floats2half2_rn(f0[4 * i + 1][dt], v1);
                    hv[4 * i + 2][dt] = __floats2half2_rn(f0[4 * i + 2][dt], v2);
                    hv[4 * i + 3][dt] = __floats2half2_rn(f0[4 * i + 3][dt], v3);
                }
            }
        }
    }
    size_t m0 = (size_t)b * 1024 + ty * 32 + 4 * q;
#pragma unroll
    for (int t = 0; t < 16; t++)
        *reinterpret_cast<uint4*>(&g_V[((size_t)t * 256 + kk) * 16384 + m0]) =
            *reinterpret_cast<const uint4*>(hv[t]);
}

// ---------------- Winograd-domain GEMM (unchanged) ----------------
__device__ __forceinline__ void mma16816(float& c0, float& c1, float& c2, float& c3,
                                         uint32_t a0, uint32_t a1, uint32_t a2, uint32_t a3,
                                         uint32_t b0, uint32_t b1) {
    asm volatile(
        "mma.sync.aligned.m16n8k16.row.col.f32.f16.f16.f32 "
        "{%0,%1,%2,%3}, {%4,%5,%6,%7}, {%8,%9}, {%0,%1,%2,%3};\n"
        : "+f"(c0), "+f"(c1), "+f"(c2), "+f"(c3)
        : "r"(a0), "r"(a1), "r"(a2), "r"(a3), "r"(b0), "r"(b1));
}
__device__ __forceinline__ void cp16(uint32_t dst, const void* src) {
    asm volatile("cp.async.cg.shared.global [%0], [%1], 16;\n" :: "r"(dst), "l"(src));
}
__device__ __forceinline__ void cp_commit() {
    asm volatile("cp.async.commit_group;\n" ::: "memory");
}

#define AS_K 264
#define BS_K 72
#define STGH (8 * AS_K + 8 * BS_K)

__global__ void __launch_bounds__(256, 2) wg_kernel() {
    extern __shared__ __align__(16) __half2 sm[];
    const int t  = blockIdx.z;
    const int n0 = blockIdx.y * 64;
    const int MB0 = blockIdx.x * 256;
    const int tid = threadIdx.x, w = tid >> 5, lane = tid & 31;
    const int g = lane >> 2, t4 = lane & 3;
    const uint32_t sb = (uint32_t)__cvta_generic_to_shared(sm);

    float acc[64];
#pragma unroll
    for (int i = 0; i < 64; i++) acc[i] = 0.f;

    auto load = [&](int kc, int st) {
        uint32_t base = sb + (uint32_t)(st * STGH) * 4u;
#pragma unroll
        for (int i = 0; i < 2; i++) {
            int id2 = tid + i * 256;
            int kkL = id2 >> 6, v = id2 & 63;
            cp16(base + (uint32_t)(kkL * AS_K) * 4u + v * 16u,
                 g_V + ((size_t)(t * 256 + kc * 8 + kkL)) * 16384 + MB0 + v * 4);
        }
        if (tid < 128) {
            int kkL = tid >> 4, v = tid & 15;
            cp16(base + (uint32_t)(8 * AS_K + kkL * BS_K) * 4u + v * 16u,
                 g_U + ((size_t)(t * 256 + kc * 8 + kkL)) * 512 + n0 + v * 4);
        }
    };
    load(0, 0); cp_commit();
    load(1, 1); cp_commit();
    load(2, 2); cp_commit();

#pragma unroll 1
    for (int c = 0; c < 32; c++) {
        if (c <= 29)      asm volatile("cp.async.wait_group 2;\n" ::: "memory");
        else if (c == 30) asm volatile("cp.async.wait_group 1;\n" ::: "memory");
        else              asm volatile("cp.async.wait_group 0;\n" ::: "memory");
        __syncthreads();
        if (c + 3 < 32) { load(c + 3, (c + 3) & 3); cp_commit(); }

        const __half2* As = sm + (c & 3) * STGH;
        const __half2* Bs = As + 8 * AS_K;
        uint32_t a[2][4];
#pragma unroll
        for (int s = 0; s < 2; s++) {
            int mc = w * 32 + s * 16 + g;
            const __half2* ab = As + t4 * AS_K + mc;
            a[s][0] = *reinterpret_cast<const uint32_t*>(ab);
            a[s][1] = *reinterpret_cast<const uint32_t*>(ab + 8);
            a[s][2] = *reinterpret_cast<const uint32_t*>(ab + 4 * AS_K);
            a[s][3] = *reinterpret_cast<const uint32_t*>(ab + 4 * AS_K + 8);
        }
#pragma unroll
        for (int nc = 0; nc < 8; nc++) {
            const __half2* bb = Bs + t4 * BS_K + nc * 8 + g;
            uint32_t b0 = *reinterpret_cast<const uint32_t*>(bb);
            uint32_t b1 = *reinterpret_cast<const uint32_t*>(bb + 4 * BS_K);
#pragma unroll
            for (int s = 0; s < 2; s++) {
                float* cc = acc + (s * 8 + nc) * 4;
                mma16816(cc[0], cc[1], cc[2], cc[3],
                         a[s][0], a[s][1], a[s][2], a[s][3], b0, b1);
            }
        }
    }

#pragma unroll
    for (int s = 0; s < 2; s++) {
        int m0 = MB0 + w * 32 + s * 16 + g;
#pragma unroll
        for (int nc = 0; nc < 8; nc++) {
            int opair = (n0 + nc * 8) / 2 + t4;
            float* cc = acc + (s * 8 + nc) * 4;
            size_t zi = ((size_t)(t * 256 + opair)) * 16384;
            g_Z[zi + m0]     = __floats2half2_rn(cc[0], cc[1]);
            g_Z[zi + m0 + 8] = __floats2half2_rn(cc[2], cc[3]);
        }
    }
}

// ---------------- output transform: 4 tiles/thread, vectorized ----------------
__global__ void __launch_bounds__(256) ot_kernel(float* __restrict__ out) {
    int idx = blockIdx.x * 256 + threadIdx.x;   // 1,048,576
    int q     = idx & 7;
    int ty    = (idx >> 3) & 31;
    int opair = (idx >> 8) & 255;
    int b     = idx >> 16;
    size_t m0 = (size_t)b * 1024 + ty * 32 + 4 * q;

    uint4 z[16];
#pragma unroll
    for (int t = 0; t < 16; t++)
        z[t] = *reinterpret_cast<const uint4*>(&g_Z[((size_t)t * 256 + opair) * 16384 + m0]);

    float dm[2];
    dm[0] = g_demod[b * 512 + 2 * opair];
    dm[1] = g_demod[b * 512 + 2 * opair + 1];

    float o[2][2][8];   // [ch][row][x]
#pragma unroll
    for (int dt = 0; dt < 4; dt++) {
        float2 F[16];
#pragma unroll
        for (int t = 0; t < 16; t++)
            F[t] = __half22float2(reinterpret_cast<const __half2*>(&z[t])[dt]);
#pragma unroll
        for (int ch = 0; ch < 2; ch++) {
            float M[16];
#pragma unroll
            for (int t = 0; t < 16; t++) M[t] = ch ? F[t].y : F[t].x;
            float T0[4], T1[4];
#pragma unroll
            for (int j = 0; j < 4; j++) {
                T0[j] = M[j] + M[4 + j] + M[8 + j];
                T1[j] = M[4 + j] - M[8 + j] - M[12 + j];
            }
            float d = dm[ch];
            o[ch][0][2 * dt]     = (T0[0] + T0[1] + T0[2]) * d;
            o[ch][0][2 * dt + 1] = (T0[1] - T0[2] - T0[3]) * d;
            o[ch][1][2 * dt]     = (T1[0] + T1[1] + T1[2]) * d;
            o[ch][1][2 * dt + 1] = (T1[1] - T1[2] - T1[3]) * d;
        }
    }

    float* base = out + ((size_t)b * 512 + 2 * opair) * 4096 + (2 * ty) * 64 + 8 * q;
#pragma unroll
    for (int ch = 0; ch < 2; ch++)
#pragma unroll
        for (int r = 0; r < 2; r++) {
            float* p = base + (size_t)ch * 4096 + r * 64;
            *reinterpret_cast<float4*>(p)     = make_float4(o[ch][r][0], o[ch][r][1],
                                                            o[ch][r][2], o[ch][r][3]);
            *reinterpret_cast<float4*>(p + 4) = make_float4(o[ch][r][4], o[ch][r][5],
                                                            o[ch][r][6], o[ch][r][7]);
        }
}

// ---------------- launch ----------------
extern "C" void kernel_launch(void* const* d_in, const int* in_sizes, int n_in,
                              void* d_out, int out_size) {
    const float* x      = (const float*)d_in[0];
    const float* w      = (const float*)d_in[1];
    const float* weight = (const float*)d_in[2];
    const float* mw     = (const float*)d_in[3];
    const float* mb     = (const float*)d_in[4];
    float* out = (float*)d_out;

    style_kernel<<<16, 512>>>(w, mw, mb);
    wsq_kernel<<<512, 512>>>(weight);
    demod_kernel<<<32, 256>>>();
    ut_kernel<<<512, 256>>>(weight);
    vt_kernel<<<4096, 256>>>(x);

    dim3 grid(64, 8, 16);   // (M/256, N/64, t)
    wg_kernel<<<grid, 256, 4 * STGH * 4>>>();

    ot_kernel<<<4096, 256>>>(out);
}

// round 10
// speedup vs baseline: 1.5771x; 1.0774x over previous
#include <cuda_runtime.h>
#include <cuda_fp16.h>
#include <cstdint>

#define NB 16

static __device__ float   g_style[NB * 512];
static __device__ float   g_wsq[512 * 512];
static __device__ float   g_demod[NB * 512];
static __device__ __half2 g_V[(size_t)16 * 256 * 16384];  // [t][kk][m]
static __device__ __half2 g_U[(size_t)16 * 256 * 512];    // [t][kk][o]
static __device__ __half2 g_Z[(size_t)16 * 256 * 16384];  // [t][opair][m]

// ---------------- small prep ----------------
__global__ void style_kernel(const float* __restrict__ w, const float* __restrict__ mw,
                             const float* __restrict__ mb) {
    __shared__ float sw[512];
    int b = blockIdx.x, c = threadIdx.x;
    sw[c] = w[b * 512 + c];
    __syncthreads();
    float acc = 0.f;
    const float* row = mw + c * 512;
#pragma unroll 8
    for (int d = 0; d < 512; d++) acc += sw[d] * row[d];
    g_style[b * 512 + c] = acc * 0.04419417382415922f + mb[c];
}
__global__ void wsq_kernel(const float* __restrict__ weight) {
    int o = blockIdx.x, c = threadIdx.x;
    const float* p = weight + (o * 512 + c) * 9;
    float s = 0.f;
#pragma unroll
    for (int t = 0; t < 9; t++) { float v = p[t]; s += v * v; }
    g_wsq[o * 512 + c] = s;
}
__global__ void demod_kernel() {
    int gid = blockIdx.x * blockDim.x + threadIdx.x;
    int o = gid >> 4, b = gid & 15;
    const float* wq = g_wsq + o * 512;
    const float* st = g_style + b * 512;
    float s = 0.f;
#pragma unroll 8
    for (int c = 0; c < 512; c++) { float t = st[c]; s += wq[c] * t * t; }
    g_demod[b * 512 + o] = rsqrtf(s * (1.f / 4608.f) + 1e-8f);
}

// ---------------- U = G w G^T ----------------
__global__ void ut_kernel(const float* __restrict__ weight) {
    int idx = blockIdx.x * 256 + threadIdx.x;
    int o = idx & 511, kk = idx >> 9;
    const float WG = 0.014731391274719739f;
    float u[2][4][4];
#pragma unroll
    for (int ch = 0; ch < 2; ch++) {
        const float* wp = weight + ((size_t)o * 512 + 2 * kk + ch) * 9;
        float tmp[4][3];
#pragma unroll
        for (int c = 0; c < 3; c++) {
            float w0 = wp[c], w1 = wp[3 + c], w2 = wp[6 + c];
            tmp[0][c] = w0;
            tmp[1][c] = 0.5f * (w0 + w1 + w2);
            tmp[2][c] = 0.5f * (w0 - w1 + w2);
            tmp[3][c] = w2;
        }
#pragma unroll
        for (int i = 0; i < 4; i++) {
            float t0 = tmp[i][0], t1 = tmp[i][1], t2 = tmp[i][2];
            u[ch][i][0] = t0 * WG;
            u[ch][i][1] = 0.5f * (t0 + t1 + t2) * WG;
            u[ch][i][2] = 0.5f * (t0 - t1 + t2) * WG;
            u[ch][i][3] = t2 * WG;
        }
    }
#pragma unroll
    for (int t = 0; t < 16; t++)
        g_U[((size_t)t * 256 + kk) * 512 + o] =
            __floats2half2_rn(u[0][t >> 2][t & 3], u[1][t >> 2][t & 3]);
}

// ---------------- V = B^T (style*x) B : 4 tiles/thread ----------------
__global__ void __launch_bounds__(256) vt_kernel(const float* __restrict__ x) {
    int idx = blockIdx.x * 256 + threadIdx.x;
    int q  = idx & 7;
    int ty = (idx >> 3) & 31;
    int kk = (idx >> 8) & 255;
    int b  = idx >> 16;
    float s[2];
    s[0] = g_style[b * 512 + 2 * kk];
    s[1] = g_style[b * 512 + 2 * kk + 1];

    float f0[16][4];
    __half2 hv[16][4];

#pragma unroll
    for (int ch = 0; ch < 2; ch++) {
        const float* xp = x + ((size_t)(b * 512 + 2 * kk + ch)) * 4096;
        float d[4][10];
        int y0 = 2 * ty - 1;
        int xl = 8 * q - 1;
#pragma unroll
        for (int r = 0; r < 4; r++) {
            int y = y0 + r;
            bool vy = (y >= 0) && (y < 64);
            const float* row = xp + y * 64;
            float4 A = make_float4(0.f, 0.f, 0.f, 0.f), B = A;
            if (vy) {
                A = *reinterpret_cast<const float4*>(row + 8 * q);
                B = *reinterpret_cast<const float4*>(row + 8 * q + 4);
            }
            float sc = s[ch];
            d[r][0] = (vy && q > 0) ? row[xl] * sc : 0.f;
            d[r][1] = A.x * sc; d[r][2] = A.y * sc; d[r][3] = A.z * sc; d[r][4] = A.w * sc;
            d[r][5] = B.x * sc; d[r][6] = B.y * sc; d[r][7] = B.z * sc; d[r][8] = B.w * sc;
            d[r][9] = (vy && q < 7) ? row[8 * q + 8] * sc : 0.f;
        }
        float p[4][10];
#pragma unroll
        for (int c = 0; c < 10; c++) {
            p[0][c] = d[0][c] - d[2][c];
            p[1][c] = d[1][c] + d[2][c];
            p[2][c] = d[2][c] - d[1][c];
            p[3][c] = d[1][c] - d[3][c];
        }
#pragma unroll
        for (int dt = 0; dt < 4; dt++) {
            int cl = 2 * dt;
#pragma unroll
            for (int i = 0; i < 4; i++) {
                float v0 = p[i][cl]     - p[i][cl + 2];
                float v1 = p[i][cl + 1] + p[i][cl + 2];
                float v2 = p[i][cl + 2] - p[i][cl + 1];
                float v3 = p[i][cl + 1] - p[i][cl + 3];
                if (ch == 0) {
                    f0[4 * i + 0][dt] = v0; f0[4 * i + 1][dt] = v1;
                    f0[4 * i + 2][dt] = v2; f0[4 * i + 3][dt] = v3;
                } else {
                    hv[4 * i + 0][dt] = __floats2half2_rn(f0[4 * i + 0][dt], v0);
                    hv[4 * i + 1][dt] = __floats2half2_rn(f0[4 * i + 1][dt], v1);
                    hv[4 * i + 2][dt] = __floats2half2_rn(f0[4 * i + 2][dt], v2);
                    hv[4 * i + 3][dt] = __floats2half2_rn(f0[4 * i + 3][dt], v3);
                }
            }
        }
    }
    size_t m0 = (size_t)b * 1024 + ty * 32 + 4 * q;
#pragma unroll
    for (int t = 0; t < 16; t++)
        *reinterpret_cast<uint4*>(&g_V[((size_t)t * 256 + kk) * 16384 + m0]) =
            *reinterpret_cast<const uint4*>(hv[t]);
}

// ---------------- Winograd GEMM: m64n64 warp tiles, 128-thread CTAs ----------------
__device__ __forceinline__ void mma16816(float& c0, float& c1, float& c2, float& c3,
                                         uint32_t a0, uint32_t a1, uint32_t a2, uint32_t a3,
                                         uint32_t b0, uint32_t b1) {
    asm volatile(
        "mma.sync.aligned.m16n8k16.row.col.f32.f16.f16.f32 "
        "{%0,%1,%2,%3}, {%4,%5,%6,%7}, {%8,%9}, {%0,%1,%2,%3};\n"
        : "+f"(c0), "+f"(c1), "+f"(c2), "+f"(c3)
        : "r"(a0), "r"(a1), "r"(a2), "r"(a3), "r"(b0), "r"(b1));
}
__device__ __forceinline__ void cp16(uint32_t dst, const void* src) {
    asm volatile("cp.async.cg.shared.global [%0], [%1], 16;\n" :: "r"(dst), "l"(src));
}
__device__ __forceinline__ void cp_commit() {
    asm volatile("cp.async.commit_group;\n" ::: "memory");
}

#define AS_K 136                        // half2 per kk row (128 m + 8 pad)
#define BS_K 136                        // half2 per kk row (128 o + 8 pad)
#define STGH (8 * AS_K + 8 * BS_K)      // 2176 half2 = 8704 B per stage

__global__ void __launch_bounds__(128) wg_kernel() {
    extern __shared__ __align__(16) __half2 sm[];
    const int t   = blockIdx.z;
    const int o0  = blockIdx.y * 128;        // out-channel base (128 channels)
    const int MB0 = blockIdx.x * 128;
    const int tid = threadIdx.x, w = tid >> 5, lane = tid & 31;
    const int g = lane >> 2, t4 = lane & 3;
    const int wm = (w & 1) * 64;             // warp m offset
    const int wo = (w >> 1) * 64;            // warp out-ch offset (local)
    const uint32_t sb = (uint32_t)__cvta_generic_to_shared(sm);

    float acc[32][4];
#pragma unroll
    for (int i = 0; i < 32; i++)
#pragma unroll
        for (int j = 0; j < 4; j++) acc[i][j] = 0.f;

    auto load = [&](int kc, int st) {
        uint32_t base = sb + (uint32_t)(st * STGH) * 4u;
#pragma unroll
        for (int i = 0; i < 2; i++) {                        // A: 256 vec16
            int id2 = tid + i * 128;
            int kkL = id2 >> 5, v = id2 & 31;
            cp16(base + (uint32_t)(kkL * AS_K) * 4u + v * 16u,
                 g_V + ((size_t)(t * 256 + kc * 8 + kkL)) * 16384 + MB0 + v * 4);
        }
#pragma unroll
        for (int i = 0; i < 2; i++) {                        // B: 256 vec16
            int id2 = tid + i * 128;
            int kkL = id2 >> 5, v = id2 & 31;
            cp16(base + (uint32_t)(8 * AS_K + kkL * BS_K) * 4u + v * 16u,
                 g_U + ((size_t)(t * 256 + kc * 8 + kkL)) * 512 + o0 + v * 4);
        }
    };
    load(0, 0); cp_commit();
    load(1, 1); cp_commit();
    load(2, 2); cp_commit();

#pragma unroll 1
    for (int c = 0; c < 32; c++) {
        if (c <= 29)      asm volatile("cp.async.wait_group 2;\n" ::: "memory");
        else if (c == 30) asm volatile("cp.async.wait_group 1;\n" ::: "memory");
        else              asm volatile("cp.async.wait_group 0;\n" ::: "memory");
        __syncthreads();
        if (c + 3 < 32) { load(c + 3, (c + 3) & 3); cp_commit(); }

        const __half2* As = sm + (c & 3) * STGH;
        const __half2* Bs = As + 8 * AS_K;

        uint32_t a[4][4];
#pragma unroll
        for (int ms = 0; ms < 4; ms++) {
            const __half2* ab = As + t4 * AS_K + wm + ms * 16 + g;
            a[ms][0] = *reinterpret_cast<const uint32_t*>(ab);
            a[ms][1] = *reinterpret_cast<const uint32_t*>(ab + 8);
            a[ms][2] = *reinterpret_cast<const uint32_t*>(ab + 4 * AS_K);
            a[ms][3] = *reinterpret_cast<const uint32_t*>(ab + 4 * AS_K + 8);
        }
        uint32_t bf[8][2];
#pragma unroll
        for (int nc = 0; nc < 8; nc++) {
            const __half2* bb = Bs + t4 * BS_K + wo + nc * 8 + g;
            bf[nc][0] = *reinterpret_cast<const uint32_t*>(bb);
            bf[nc][1] = *reinterpret_cast<const uint32_t*>(bb + 4 * BS_K);
        }
#pragma unroll
        for (int nc = 0; nc < 8; nc++)
#pragma unroll
            for (int ms = 0; ms < 4; ms++) {
                float* cc = acc[ms * 8 + nc];
                mma16816(cc[0], cc[1], cc[2], cc[3],
                         a[ms][0], a[ms][1], a[ms][2], a[ms][3],
                         bf[nc][0], bf[nc][1]);
            }
    }

    // epilogue: Z fp16, half2 = (o even, o odd)
#pragma unroll
    for (int ms = 0; ms < 4; ms++) {
        int m0 = MB0 + wm + ms * 16 + g;
#pragma unroll
        for (int nc = 0; nc < 8; nc++) {
            int opair = (o0 + wo + nc * 8) / 2 + t4;
            float* cc = acc[ms * 8 + nc];
            size_t zi = ((size_t)(t * 256 + opair)) * 16384;
            g_Z[zi + m0]     = __floats2half2_rn(cc[0], cc[1]);
            g_Z[zi + m0 + 8] = __floats2half2_rn(cc[2], cc[3]);
        }
    }
}

// ---------------- output transform: 4 tiles/thread ----------------
__global__ void __launch_bounds__(256) ot_kernel(float* __restrict__ out) {
    int idx = blockIdx.x * 256 + threadIdx.x;
    int q     = idx & 7;
    int ty    = (idx >> 3) & 31;
    int opair = (idx >> 8) & 255;
    int b     = idx >> 16;
    size_t m0 = (size_t)b * 1024 + ty * 32 + 4 * q;

    uint4 z[16];
#pragma unroll
    for (int t = 0; t < 16; t++)
        z[t] = *reinterpret_cast<const uint4*>(&g_Z[((size_t)t * 256 + opair) * 16384 + m0]);

    float dm[2];
    dm[0] = g_demod[b * 512 + 2 * opair];
    dm[1] = g_demod[b * 512 + 2 * opair + 1];

    float o[2][2][8];
#pragma unroll
    for (int dt = 0; dt < 4; dt++) {
        float2 F[16];
#pragma unroll
        for (int t = 0; t < 16; t++)
            F[t] = __half22float2(reinterpret_cast<const __half2*>(&z[t])[dt]);
#pragma unroll
        for (int ch = 0; ch < 2; ch++) {
            float M[16];
#pragma unroll
            for (int t = 0; t < 16; t++) M[t] = ch ? F[t].y : F[t].x;
            float T0[4], T1[4];
#pragma unroll
            for (int j = 0; j < 4; j++) {
                T0[j] = M[j] + M[4 + j] + M[8 + j];
                T1[j] = M[4 + j] - M[8 + j] - M[12 + j];
            }
            float d = dm[ch];
            o[ch][0][2 * dt]     = (T0[0] + T0[1] + T0[2]) * d;
            o[ch][0][2 * dt + 1] = (T0[1] - T0[2] - T0[3]) * d;
            o[ch][1][2 * dt]     = (T1[0] + T1[1] + T1[2]) * d;
            o[ch][1][2 * dt + 1] = (T1[1] - T1[2] - T1[3]) * d;
        }
    }

    float* base = out + ((size_t)b * 512 + 2 * opair) * 4096 + (2 * ty) * 64 + 8 * q;
#pragma unroll
    for (int ch = 0; ch < 2; ch++)
#pragma unroll
        for (int r = 0; r < 2; r++) {
            float* p = base + (size_t)ch * 4096 + r * 64;
            *reinterpret_cast<float4*>(p)     = make_float4(o[ch][r][0], o[ch][r][1],
                                                            o[ch][r][2], o[ch][r][3]);
            *reinterpret_cast<float4*>(p + 4) = make_float4(o[ch][r][4], o[ch][r][5],
                                                            o[ch][r][6], o[ch][r][7]);
        }
}

// ---------------- launch ----------------
extern "C" void kernel_launch(void* const* d_in, const int* in_sizes, int n_in,
                              void* d_out, int out_size) {
    const float* x      = (const float*)d_in[0];
    const float* w      = (const float*)d_in[1];
    const float* weight = (const float*)d_in[2];
    const float* mw     = (const float*)d_in[3];
    const float* mb     = (const float*)d_in[4];
    float* out = (float*)d_out;

    style_kernel<<<16, 512>>>(w, mw, mb);
    wsq_kernel<<<512, 512>>>(weight);
    demod_kernel<<<32, 256>>>();
    ut_kernel<<<512, 256>>>(weight);
    vt_kernel<<<4096, 256>>>(x);

    dim3 grid(128, 4, 16);   // (M/128, N/128, t)
    wg_kernel<<<grid, 128, 4 * STGH * 4>>>();

    ot_kernel<<<4096, 256>>>(out);
}